// round 12
// baseline (speedup 1.0000x reference)
#include <cuda_runtime.h>
#include <cuda_fp16.h>
#include <cstdint>

// Problem constants (fixed by the dataset)
#define MROWS 8192
#define NCOLS 8192
#define KROWS 8192
#define NNZ   256
#define BATCH 32

// fp16 copies: x (converted once per launch) and intermediate bx. 512 KB each.
__device__ __half g_xh[NCOLS * BATCH];
__device__ __half g_bx[KROWS * BATCH];

// ── Convert x to fp16. 262144 floats; each thread handles one float4 -> uint2.
__global__ void __launch_bounds__(256)
x_to_half_kernel(const float* __restrict__ x, __half* __restrict__ xh)
{
    const int i = blockIdx.x * blockDim.x + threadIdx.x;   // 0..65535 float4s
    const float4 v = reinterpret_cast<const float4*>(x)[i];
    const __half2 h0 = __floats2half2_rn(v.x, v.y);
    const __half2 h1 = __floats2half2_rn(v.z, v.w);
    uint2 s;
    s.x = *reinterpret_cast<const unsigned*>(&h0);
    s.y = *reinterpret_cast<const unsigned*>(&h1);
    reinterpret_cast<uint2*>(xh)[i] = s;
}

// Shared gather geometry (proven best: quad-line fp16):
//   warp = one output row; g = lane>>3 (nnz subgroup), c = lane&7 (batch quad)
//   LDG.64 gathers 4 distinct fully-used 64B rows per instruction.

// ── Stage 1: bx = fp16(B @ xh). fp16 gathers, fp32 accumulate, fp16 row store.
__global__ void __launch_bounds__(256)
ell_stage1_kernel(const int*    __restrict__ idx,
                  const float*  __restrict__ vals,
                  const __half* __restrict__ src,
                  __half*       __restrict__ dst)
{
    __shared__ __align__(16) uint2 s_pair[8][NNZ];

    const int warp = threadIdx.x >> 5;
    const int lane = threadIdx.x & 31;
    const int g    = lane >> 3;
    const int c    = lane & 7;
    const int row  = blockIdx.x * 8 + warp;

    {
        const int4*   ip = reinterpret_cast<const int4*>(idx  + (size_t)row * NNZ);
        const float4* vp = reinterpret_cast<const float4*>(vals + (size_t)row * NNZ);
#pragma unroll
        for (int q = 0; q < NNZ / (32 * 4); ++q) {
            const int4   iv = ip[q * 32 + lane];
            const float4 vv = vp[q * 32 + lane];
            const int base = (q * 32 + lane) * 4;
            s_pair[warp][base + 0] = make_uint2((unsigned)iv.x, __float_as_uint(vv.x));
            s_pair[warp][base + 1] = make_uint2((unsigned)iv.y, __float_as_uint(vv.y));
            s_pair[warp][base + 2] = make_uint2((unsigned)iv.z, __float_as_uint(vv.z));
            s_pair[warp][base + 3] = make_uint2((unsigned)iv.w, __float_as_uint(vv.w));
        }
    }
    __syncwarp();

    const uint2* src2 = reinterpret_cast<const uint2*>(src) + c;  // lane's 8B slice
    float4 acc = make_float4(0.f, 0.f, 0.f, 0.f);

#pragma unroll 4
    for (int t = 0; t < NNZ / 4; ++t) {
        const uint2 p = s_pair[warp][t * 4 + g];                  // LDS.64 metadata
        const uint2 d = __ldg(&src2[(size_t)p.x * (BATCH / 4)]);  // 4x64B lines/instr
        const float v = __uint_as_float(p.y);
        const float2 f0 = __half22float2(*reinterpret_cast<const __half2*>(&d.x));
        const float2 f1 = __half22float2(*reinterpret_cast<const __half2*>(&d.y));
        acc.x = fmaf(v, f0.x, acc.x);
        acc.y = fmaf(v, f0.y, acc.y);
        acc.z = fmaf(v, f1.x, acc.z);
        acc.w = fmaf(v, f1.y, acc.w);
    }

#pragma unroll
    for (int off = 8; off < 32; off <<= 1) {
        acc.x += __shfl_xor_sync(0xffffffffu, acc.x, off);
        acc.y += __shfl_xor_sync(0xffffffffu, acc.y, off);
        acc.z += __shfl_xor_sync(0xffffffffu, acc.z, off);
        acc.w += __shfl_xor_sync(0xffffffffu, acc.w, off);
    }

    if (g == 0) {  // one contiguous 64B fp16 row per warp
        const __half2 h0 = __floats2half2_rn(acc.x, acc.y);
        const __half2 h1 = __floats2half2_rn(acc.z, acc.w);
        uint2 s;
        s.x = *reinterpret_cast<const unsigned*>(&h0);
        s.y = *reinterpret_cast<const unsigned*>(&h1);
        reinterpret_cast<uint2*>(dst + (size_t)row * BATCH)[c] = s;
    }
}

// ── Stage 2: out[b][m] = (A @ bx). fp16 gathers, fp32 accumulate; results
//    transposed through smem so the CTA writes 32 coalesced 32B segments
//    instead of 256 scattered 4B stores (8x fewer store wavefronts).
__global__ void __launch_bounds__(256)
ell_stage2_kernel(const int*    __restrict__ idx,
                  const float*  __restrict__ vals,
                  const __half* __restrict__ src,
                  float*        __restrict__ dst)
{
    __shared__ __align__(16) uint2 s_pair[8][NNZ];
    __shared__ float s_out[BATCH][9];   // [b][warp], pad 9 to dodge bank conflicts

    const int warp = threadIdx.x >> 5;
    const int lane = threadIdx.x & 31;
    const int g    = lane >> 3;
    const int c    = lane & 7;
    const int row  = blockIdx.x * 8 + warp;

    {
        const int4*   ip = reinterpret_cast<const int4*>(idx  + (size_t)row * NNZ);
        const float4* vp = reinterpret_cast<const float4*>(vals + (size_t)row * NNZ);
#pragma unroll
        for (int q = 0; q < NNZ / (32 * 4); ++q) {
            const int4   iv = ip[q * 32 + lane];
            const float4 vv = vp[q * 32 + lane];
            const int base = (q * 32 + lane) * 4;
            s_pair[warp][base + 0] = make_uint2((unsigned)iv.x, __float_as_uint(vv.x));
            s_pair[warp][base + 1] = make_uint2((unsigned)iv.y, __float_as_uint(vv.y));
            s_pair[warp][base + 2] = make_uint2((unsigned)iv.z, __float_as_uint(vv.z));
            s_pair[warp][base + 3] = make_uint2((unsigned)iv.w, __float_as_uint(vv.w));
        }
    }
    __syncwarp();

    const uint2* src2 = reinterpret_cast<const uint2*>(src) + c;
    float4 acc = make_float4(0.f, 0.f, 0.f, 0.f);

#pragma unroll 4
    for (int t = 0; t < NNZ / 4; ++t) {
        const uint2 p = s_pair[warp][t * 4 + g];
        const uint2 d = __ldg(&src2[(size_t)p.x * (BATCH / 4)]);
        const float v = __uint_as_float(p.y);
        const float2 f0 = __half22float2(*reinterpret_cast<const __half2*>(&d.x));
        const float2 f1 = __half22float2(*reinterpret_cast<const __half2*>(&d.y));
        acc.x = fmaf(v, f0.x, acc.x);
        acc.y = fmaf(v, f0.y, acc.y);
        acc.z = fmaf(v, f1.x, acc.z);
        acc.w = fmaf(v, f1.y, acc.w);
    }

#pragma unroll
    for (int off = 8; off < 32; off <<= 1) {
        acc.x += __shfl_xor_sync(0xffffffffu, acc.x, off);
        acc.y += __shfl_xor_sync(0xffffffffu, acc.y, off);
        acc.z += __shfl_xor_sync(0xffffffffu, acc.z, off);
        acc.w += __shfl_xor_sync(0xffffffffu, acc.w, off);
    }

    if (g == 0) {   // lanes 0..7 hold batches 4c..4c+3 of this warp's row
        s_out[4 * c + 0][warp] = acc.x;
        s_out[4 * c + 1][warp] = acc.y;
        s_out[4 * c + 2][warp] = acc.z;
        s_out[4 * c + 3][warp] = acc.w;
    }
    __syncthreads();

    // 256 threads write the CTA's 32x8 transposed block: thread t -> batch t/8,
    // local row t%8. Each 8-lane group stores one contiguous 32B segment.
    {
        const int b = threadIdx.x >> 3;
        const int j = threadIdx.x & 7;
        dst[(size_t)b * MROWS + blockIdx.x * 8 + j] = s_out[b][j];
    }
}

extern "C" void kernel_launch(void* const* d_in, const int* in_sizes, int n_in,
                              void* d_out, int out_size)
{
    // metadata order:
    //   0: x      float32 [8192, 32]
    //   1: a_idx  int32   [8192, 256]
    //   2: a_vals float32 [8192, 256]
    //   3: b_idx  int32   [8192, 256]
    //   4: b_vals float32 [8192, 256]
    const float* x      = (const float*)d_in[0];
    const int*   a_idx  = (const int*)  d_in[1];
    const float* a_vals = (const float*)d_in[2];
    const int*   b_idx  = (const int*)  d_in[3];
    const float* b_vals = (const float*)d_in[4];
    float* out = (float*)d_out;  // (1, 32, 8192) fp32

    __half *xh, *bx;
    cudaGetSymbolAddress((void**)&xh, g_xh);
    cudaGetSymbolAddress((void**)&bx, g_bx);

    // Pre-pass: xh = fp16(x)
    x_to_half_kernel<<<(NCOLS * BATCH / 4) / 256, 256>>>(x, xh);
    // Stage 1: bx = fp16(B @ xh)
    ell_stage1_kernel<<<KROWS / 8, 256>>>(b_idx, b_vals, xh, bx);
    // Stage 2: out = (A @ bx)^T via smem transpose
    ell_stage2_kernel<<<MROWS / 8, 256>>>(a_idx, a_vals, bx, out);
}